// round 3
// baseline (speedup 1.0000x reference)
#include <cuda_runtime.h>

// loss = dot(colsum(a), colsum(b)),  a,b: [16384, 512] fp32  (2*LAMBD = 1.0)
// One fused kernel, float4 loads, single-wave grid, last-block finalize + reset.

#define ROWS 16384
#define COLS 512
#define C4   128                    // float4 columns per row
#define N4   (ROWS * C4)            // total float4 per matrix = 2,097,152
#define NBLK 296                    // 2 CTAs x 148 SMs = one wave
#define TPB  512
#define NT   (NBLK * TPB)           // 151,552 (multiple of 128 -> fixed col per thread)

__device__ float g_sa[COLS];        // zero at module load; re-zeroed every call
__device__ float g_sb[COLS];
__device__ unsigned int g_ticket;

__global__ __launch_bounds__(TPB) void fused_kernel(const float4* __restrict__ a,
                                                    const float4* __restrict__ b,
                                                    float* __restrict__ out) {
    const int t = threadIdx.x;

    float4 sa = make_float4(0.f, 0.f, 0.f, 0.f);
    float4 sb = make_float4(0.f, 0.f, 0.f, 0.f);

#pragma unroll 4
    for (int idx = blockIdx.x * TPB + t; idx < N4; idx += NT) {
        float4 va = a[idx];
        float4 vb = b[idx];
        sa.x += va.x; sa.y += va.y; sa.z += va.z; sa.w += va.w;
        sb.x += vb.x; sb.y += vb.y; sb.z += vb.z; sb.w += vb.w;
    }

    // block reduction: 4 threads (t, t+128, t+256, t+384) share column-quad t%128
    __shared__ float4 red_a[TPB];
    __shared__ float4 red_b[TPB];
    red_a[t] = sa;
    red_b[t] = sb;
    __syncthreads();

    if (t < C4) {
        float4 ra = red_a[t], rb = red_b[t];
#pragma unroll
        for (int k = 1; k < 4; ++k) {
            float4 xa = red_a[t + k * C4], xb = red_b[t + k * C4];
            ra.x += xa.x; ra.y += xa.y; ra.z += xa.z; ra.w += xa.w;
            rb.x += xb.x; rb.y += xb.y; rb.z += xb.z; rb.w += xb.w;
        }
        atomicAdd(&g_sa[4 * t + 0], ra.x);
        atomicAdd(&g_sa[4 * t + 1], ra.y);
        atomicAdd(&g_sa[4 * t + 2], ra.z);
        atomicAdd(&g_sa[4 * t + 3], ra.w);
        atomicAdd(&g_sb[4 * t + 0], rb.x);
        atomicAdd(&g_sb[4 * t + 1], rb.y);
        atomicAdd(&g_sb[4 * t + 2], rb.z);
        atomicAdd(&g_sb[4 * t + 3], rb.w);
    }

    // ---- last-block-done ticket ----
    __threadfence();
    __shared__ bool is_last;
    if (t == 0) {
        unsigned int tk = atomicAdd(&g_ticket, 1u);
        is_last = (tk == (unsigned)(gridDim.x - 1));
    }
    __syncthreads();
    if (!is_last) return;

    __threadfence();

    float va = __ldcg(&g_sa[t]);
    float vb = __ldcg(&g_sb[t]);
    g_sa[t] = 0.0f;                 // reset for next graph replay
    g_sb[t] = 0.0f;

    float v = va * vb;
    __shared__ float fr[16];
#pragma unroll
    for (int o = 16; o > 0; o >>= 1)
        v += __shfl_xor_sync(0xffffffffu, v, o);
    if ((t & 31) == 0) fr[t >> 5] = v;
    __syncthreads();
    if (t < 16) {
        float w = fr[t];
#pragma unroll
        for (int o = 8; o > 0; o >>= 1)
            w += __shfl_xor_sync(0xffffu, w, o);
        if (t == 0) {
            out[0] = w;             // 2 * LAMBD = 1.0
            g_ticket = 0u;
        }
    }
}

extern "C" void kernel_launch(void* const* d_in, const int* in_sizes, int n_in,
                              void* d_out, int out_size) {
    const float4* a = (const float4*)d_in[0];
    const float4* b = (const float4*)d_in[1];
    float* out = (float*)d_out;

    fused_kernel<<<NBLK, TPB>>>(a, b, out);
}

// round 4
// speedup vs baseline: 1.0123x; 1.0123x over previous
#include <cuda_runtime.h>

// loss = dot(colsum(a), colsum(b)),  a,b: [16384, 512] fp32  (2*LAMBD = 1.0)
// One fused kernel: float4 loads, COMPILE-TIME trip count (16) for load batching,
// smem block-reduce -> global atomics -> last-block finalize + state reset.

#define ROWS  16384
#define COLS  512
#define C4    128                    // float4 columns per row
#define N4    (ROWS * C4)            // 2,097,152 float4 per matrix
#define NBLK  256
#define TPB   512
#define NT    (NBLK * TPB)           // 131,072 threads; N4/NT = 16 exactly
#define TRIPS (N4 / NT)              // 16 (compile-time)

__device__ float g_sa[COLS];         // zero at module load; re-zeroed every call
__device__ float g_sb[COLS];
__device__ unsigned int g_ticket;

__global__ __launch_bounds__(TPB) void fused_kernel(const float4* __restrict__ a,
                                                    const float4* __restrict__ b,
                                                    float* __restrict__ out) {
    const int t    = threadIdx.x;
    const int base = blockIdx.x * TPB + t;

    float4 sa = make_float4(0.f, 0.f, 0.f, 0.f);
    float4 sb = make_float4(0.f, 0.f, 0.f, 0.f);

#pragma unroll 8
    for (int i = 0; i < TRIPS; ++i) {        // constant bound -> batched LDG.128
        float4 va = a[base + i * NT];
        float4 vb = b[base + i * NT];
        sa.x += va.x; sa.y += va.y; sa.z += va.z; sa.w += va.w;
        sb.x += vb.x; sb.y += vb.y; sb.z += vb.z; sb.w += vb.w;
    }

    // block reduction: threads t, t+128, t+256, t+384 share float4-column t%128
    __shared__ float4 red_a[TPB];
    __shared__ float4 red_b[TPB];
    red_a[t] = sa;
    red_b[t] = sb;
    __syncthreads();

    if (t < C4) {
        float4 ra = red_a[t], rb = red_b[t];
#pragma unroll
        for (int k = 1; k < 4; ++k) {
            float4 xa = red_a[t + k * C4], xb = red_b[t + k * C4];
            ra.x += xa.x; ra.y += xa.y; ra.z += xa.z; ra.w += xa.w;
            rb.x += xb.x; rb.y += xb.y; rb.z += xb.z; rb.w += xb.w;
        }
        atomicAdd(&g_sa[4 * t + 0], ra.x);
        atomicAdd(&g_sa[4 * t + 1], ra.y);
        atomicAdd(&g_sa[4 * t + 2], ra.z);
        atomicAdd(&g_sa[4 * t + 3], ra.w);
        atomicAdd(&g_sb[4 * t + 0], rb.x);
        atomicAdd(&g_sb[4 * t + 1], rb.y);
        atomicAdd(&g_sb[4 * t + 2], rb.z);
        atomicAdd(&g_sb[4 * t + 3], rb.w);
    }

    // ---- last-block-done ticket ----
    __threadfence();
    __shared__ bool is_last;
    if (t == 0) {
        unsigned int tk = atomicAdd(&g_ticket, 1u);
        is_last = (tk == (unsigned)(gridDim.x - 1));
    }
    __syncthreads();
    if (!is_last) return;

    __threadfence();

    float va = __ldcg(&g_sa[t]);
    float vb = __ldcg(&g_sb[t]);
    g_sa[t] = 0.0f;                  // reset for next graph replay
    g_sb[t] = 0.0f;

    float v = va * vb;
    __shared__ float fr[16];
#pragma unroll
    for (int o = 16; o > 0; o >>= 1)
        v += __shfl_xor_sync(0xffffffffu, v, o);
    if ((t & 31) == 0) fr[t >> 5] = v;
    __syncthreads();
    if (t < 16) {
        float w = fr[t];
#pragma unroll
        for (int o = 8; o > 0; o >>= 1)
            w += __shfl_xor_sync(0xffffu, w, o);
        if (t == 0) {
            out[0] = w;              // 2 * LAMBD = 1.0
            g_ticket = 0u;
        }
    }
}

extern "C" void kernel_launch(void* const* d_in, const int* in_sizes, int n_in,
                              void* d_out, int out_size) {
    const float4* a = (const float4*)d_in[0];
    const float4* b = (const float4*)d_in[1];
    float* out = (float*)d_out;

    fused_kernel<<<NBLK, TPB>>>(a, b, out);
}

// round 5
// speedup vs baseline: 1.2448x; 1.2296x over previous
#include <cuda_runtime.h>

// loss = dot(colsum(a), colsum(b)),  a,b: [16384, 512] fp32  (2*LAMBD = 1.0)
// One fused kernel. SCALAR coalesced LDG.32 (1 line/warp/load — optimal L1tex
// wavefront rate on sm_103a), fine-grained grid for wave balance,
// atomics -> last-block finalize + state reset.

#define ROWS 16384
#define COLS 512
#define NBLK 1024            // fine-grained: 1024/148 ≈ 6.9 CTAs/SM -> 98.8% balance
#define TPB  512
#define RPB  (ROWS / NBLK)   // 16 rows per block (compile-time)

__device__ float g_sa[COLS];          // zero-init at module load; re-zeroed each call
__device__ float g_sb[COLS];
__device__ unsigned int g_ticket;

__global__ __launch_bounds__(TPB) void fused_kernel(const float* __restrict__ a,
                                                    const float* __restrict__ b,
                                                    float* __restrict__ out) {
    const int c  = threadIdx.x;              // column 0..511 (coalesced across warp)
    const int r0 = blockIdx.x * RPB;

    float sa = 0.0f, sb = 0.0f;
#pragma unroll 8
    for (int r = r0; r < r0 + RPB; ++r) {    // constant trip count 16
        sa += a[(size_t)r * COLS + c];
        sb += b[(size_t)r * COLS + c];
    }
    atomicAdd(&g_sa[c], sa);
    atomicAdd(&g_sb[c], sb);

    // ---- last-block-done ticket ----
    __threadfence();
    __shared__ bool is_last;
    if (c == 0) {
        unsigned int t = atomicAdd(&g_ticket, 1u);
        is_last = (t == (unsigned)(gridDim.x - 1));
    }
    __syncthreads();
    if (!is_last) return;

    __threadfence();                         // acquire side

    float va = __ldcg(&g_sa[c]);
    float vb = __ldcg(&g_sb[c]);
    g_sa[c] = 0.0f;                          // reset for next graph replay
    g_sb[c] = 0.0f;

    float v = va * vb;
    __shared__ float red[16];
#pragma unroll
    for (int o = 16; o > 0; o >>= 1)
        v += __shfl_xor_sync(0xffffffffu, v, o);
    if ((c & 31) == 0) red[c >> 5] = v;
    __syncthreads();
    if (c < 16) {
        float w = red[c];
#pragma unroll
        for (int o = 8; o > 0; o >>= 1)
            w += __shfl_xor_sync(0xffffu, w, o);
        if (c == 0) {
            out[0] = w;                      // 2 * LAMBD = 1.0
            g_ticket = 0u;
        }
    }
}

extern "C" void kernel_launch(void* const* d_in, const int* in_sizes, int n_in,
                              void* d_out, int out_size) {
    const float* a = (const float*)d_in[0];
    const float* b = (const float*)d_in[1];
    float* out = (float*)d_out;

    fused_kernel<<<NBLK, TPB>>>(a, b, out);
}

// round 6
// speedup vs baseline: 1.6118x; 1.2948x over previous
#include <cuda_runtime.h>

// loss = dot(colsum(a), colsum(b)),  a,b: [16384, 512] fp32  (2*LAMBD = 1.0)
// One fused kernel, R2 shape (proven best): 256 CTAs x 512 thr, scalar coalesced
// LDG (1 line/warp/load), deep unroll-16 batching, streaming (.cs) loads,
// atomics -> last-block finalize + state reset.

#define ROWS 16384
#define COLS 512
#define NBLK 256
#define TPB  512
#define RPB  (ROWS / NBLK)   // 64 rows per block (compile-time)

__device__ float g_sa[COLS];          // zero-init at module load; re-zeroed each call
__device__ float g_sb[COLS];
__device__ unsigned int g_ticket;

__global__ __launch_bounds__(TPB) void fused_kernel(const float* __restrict__ a,
                                                    const float* __restrict__ b,
                                                    float* __restrict__ out) {
    const int c  = threadIdx.x;              // column 0..511 (coalesced across warp)
    const int r0 = blockIdx.x * RPB;

    const float* pa = a + (size_t)r0 * COLS + c;
    const float* pb = b + (size_t)r0 * COLS + c;

    float sa = 0.0f, sb = 0.0f;
#pragma unroll 16
    for (int r = 0; r < RPB; ++r) {          // constant trip count 64, deep batch
        sa += __ldcs(pa + (size_t)r * COLS);
        sb += __ldcs(pb + (size_t)r * COLS);
    }
    atomicAdd(&g_sa[c], sa);
    atomicAdd(&g_sb[c], sb);

    // ---- last-block-done ticket ----
    __threadfence();
    __shared__ bool is_last;
    if (c == 0) {
        unsigned int t = atomicAdd(&g_ticket, 1u);
        is_last = (t == (unsigned)(gridDim.x - 1));
    }
    __syncthreads();
    if (!is_last) return;

    __threadfence();                         // acquire side

    float va = __ldcg(&g_sa[c]);
    float vb = __ldcg(&g_sb[c]);
    g_sa[c] = 0.0f;                          // reset for next graph replay
    g_sb[c] = 0.0f;

    float v = va * vb;
    __shared__ float red[16];
#pragma unroll
    for (int o = 16; o > 0; o >>= 1)
        v += __shfl_xor_sync(0xffffffffu, v, o);
    if ((c & 31) == 0) red[c >> 5] = v;
    __syncthreads();
    if (c < 16) {
        float w = red[c];
#pragma unroll
        for (int o = 8; o > 0; o >>= 1)
            w += __shfl_xor_sync(0xffffu, w, o);
        if (c == 0) {
            out[0] = w;                      // 2 * LAMBD = 1.0
            g_ticket = 0u;
        }
    }
}

extern "C" void kernel_launch(void* const* d_in, const int* in_sizes, int n_in,
                              void* d_out, int out_size) {
    const float* a = (const float*)d_in[0];
    const float* b = (const float*)d_in[1];
    float* out = (float*)d_out;

    fused_kernel<<<NBLK, TPB>>>(a, b, out);
}